// round 2
// baseline (speedup 1.0000x reference)
#include <cuda_runtime.h>
#include <cstdint>

#define NB 8
#define CC 512
#define CQ 64
#define HH 96
#define WW 96
#define HW (HH*WW)          // 9216
#define LEN 192
#define NEGV -1e30f

// ---------------- scratch (device globals; no allocation allowed) ----------------
__device__ float g_q[(size_t)NB*CQ*HW];       //  18.9 MB
__device__ float g_k[(size_t)NB*CQ*HW];       //  18.9 MB
__device__ float g_v[(size_t)NB*CC*HW];       // 151 MB
__device__ float g_e[(size_t)NB*HW*LEN];      //  56.6 MB (energy -> attn in place)

// ---------------- K1: projection GEMM ----------------
// out[n][o][p] = sum_c Wt[o][c] * x[n][c][p] + bias[o]
// A = Wt (O x 512, row-major), B = x[n] (512 x 9216), C = out[n] (O x 9216)
// BM=64, BN=128, BK=16, 256 threads, 4x8 per-thread tile. float4 staging.
__global__ __launch_bounds__(256) void proj_kernel(
    const float* __restrict__ Wt, const float* __restrict__ bias,
    const float* __restrict__ x, float* __restrict__ out, int O)
{
    __shared__ float As[16][64];    // As[k][m]
    __shared__ float Bs[16][128];   // Bs[k][n]

    const int n  = blockIdx.z;
    const int m0 = blockIdx.y * 64;
    const int p0 = blockIdx.x * 128;
    const float* B = x + (size_t)n * CC * HW;
    float* Cp      = out + (size_t)n * O * HW;

    const int tid = threadIdx.x;
    const int tm  = tid >> 4;    // 0..15
    const int tn  = tid & 15;    // 0..15

    float acc[4][8];
#pragma unroll
    for (int i = 0; i < 4; i++)
#pragma unroll
        for (int j = 0; j < 8; j++) acc[i][j] = 0.f;

    for (int k0 = 0; k0 < CC; k0 += 16) {
        // A tile: 64 rows x 16 cols = 1024 floats = 256 float4 (one per thread)
        {
            int o  = tid >> 2;          // 0..63
            int c4 = (tid & 3) * 4;     // 0,4,8,12
            float4 a4 = *(const float4*)&Wt[(size_t)(m0 + o) * CC + k0 + c4];
            As[c4 + 0][o] = a4.x;
            As[c4 + 1][o] = a4.y;
            As[c4 + 2][o] = a4.z;
            As[c4 + 3][o] = a4.w;
        }
        // B tile: 16 rows x 128 cols = 2048 floats = 512 float4 (two per thread)
#pragma unroll
        for (int i = 0; i < 2; i++) {
            int e  = tid + i * 256;       // 0..511
            int r  = e >> 5;              // 0..15
            int cl = (e & 31) * 4;        // 0..124
            *(float4*)&Bs[r][cl] = *(const float4*)&B[(size_t)(k0 + r) * HW + p0 + cl];
        }
        __syncthreads();
#pragma unroll
        for (int kk = 0; kk < 16; kk++) {
            float a[4], b[8];
#pragma unroll
            for (int i = 0; i < 4; i++) a[i] = As[kk][tm * 4 + i];
#pragma unroll
            for (int j = 0; j < 8; j++) b[j] = Bs[kk][tn * 8 + j];
#pragma unroll
            for (int i = 0; i < 4; i++)
#pragma unroll
                for (int j = 0; j < 8; j++) acc[i][j] += a[i] * b[j];
        }
        __syncthreads();
    }
#pragma unroll
    for (int i = 0; i < 4; i++) {
        int o = m0 + tm * 4 + i;
        float bv = bias[o];
        float4 s0 = make_float4(acc[i][0] + bv, acc[i][1] + bv, acc[i][2] + bv, acc[i][3] + bv);
        float4 s1 = make_float4(acc[i][4] + bv, acc[i][5] + bv, acc[i][6] + bv, acc[i][7] + bv);
        float* cp = &Cp[(size_t)o * HW + p0 + tn * 8];
        *(float4*)cp       = s0;
        *(float4*)(cp + 4) = s1;
    }
}

// ---------------- K2a: row energies ----------------
// e_row[n,h,w,v] = sum_c q[n,c,h,w] * k[n,c,h,v]   -> g_e[...][0:96]
__global__ __launch_bounds__(256) void erow_kernel()
{
    __shared__ float Qs[CQ * WW];
    __shared__ float Ks[CQ * WW];
    const int n = blockIdx.x / HH;
    const int h = blockIdx.x % HH;
    const int tid = threadIdx.x;

    const float* qb = g_q + (size_t)n * CQ * HW + (size_t)h * WW;
    const float* kb = g_k + (size_t)n * CQ * HW + (size_t)h * WW;
    for (int e = tid; e < CQ * WW; e += 256) {
        int c = e / WW, w = e % WW;
        Qs[e] = qb[(size_t)c * HW + w];
        Ks[e] = kb[(size_t)c * HW + w];
    }
    __syncthreads();

    const int tw = tid >> 4;   // w-group (6 each)
    const int tv = tid & 15;   // v-group (6 each)
    float acc[6][6];
#pragma unroll
    for (int i = 0; i < 6; i++)
#pragma unroll
        for (int j = 0; j < 6; j++) acc[i][j] = 0.f;

    for (int c = 0; c < CQ; c++) {
        float a[6], b[6];
#pragma unroll
        for (int i = 0; i < 6; i++) a[i] = Qs[c * WW + tw * 6 + i];
#pragma unroll
        for (int j = 0; j < 6; j++) b[j] = Ks[c * WW + tv * 6 + j];
#pragma unroll
        for (int i = 0; i < 6; i++)
#pragma unroll
            for (int j = 0; j < 6; j++) acc[i][j] += a[i] * b[j];
    }
    float* ep = g_e + ((size_t)(n * HH + h) * WW) * LEN;
#pragma unroll
    for (int i = 0; i < 6; i++)
#pragma unroll
        for (int j = 0; j < 6; j++)
            ep[(size_t)(tw * 6 + i) * LEN + tv * 6 + j] = acc[i][j];
}

// ---------------- K2b: column energies ----------------
// e_col[n,h,w,j] = sum_c q[n,c,h,w] * k[n,c,j,w], diag(h==j) -> NEG  -> g_e[...][96:192]
__global__ __launch_bounds__(256) void ecol_kernel()
{
    __shared__ float Qs[CQ * HH];
    __shared__ float Ks[CQ * HH];
    const int n = blockIdx.x / WW;
    const int w = blockIdx.x % WW;
    const int tid = threadIdx.x;

    for (int e = tid; e < CQ * HH; e += 256) {
        int c = e / HH, h = e % HH;
        size_t gi = ((size_t)(n * CQ + c) * HH + h) * WW + w;
        Qs[e] = g_q[gi];
        Ks[e] = g_k[gi];
    }
    __syncthreads();

    const int th = tid >> 4;
    const int tj = tid & 15;
    float acc[6][6];
#pragma unroll
    for (int i = 0; i < 6; i++)
#pragma unroll
        for (int j = 0; j < 6; j++) acc[i][j] = 0.f;

    for (int c = 0; c < CQ; c++) {
        float a[6], b[6];
#pragma unroll
        for (int i = 0; i < 6; i++) a[i] = Qs[c * HH + th * 6 + i];
#pragma unroll
        for (int j = 0; j < 6; j++) b[j] = Ks[c * HH + tj * 6 + j];
#pragma unroll
        for (int i = 0; i < 6; i++)
#pragma unroll
            for (int j = 0; j < 6; j++) acc[i][j] += a[i] * b[j];
    }
#pragma unroll
    for (int i = 0; i < 6; i++) {
        int h = th * 6 + i;
        float* ep = g_e + ((size_t)(n * HH + h) * WW + w) * LEN + WW;
#pragma unroll
        for (int j = 0; j < 6; j++) {
            int jc = tj * 6 + j;
            ep[jc] = (jc == h) ? NEGV : acc[i][j];
        }
    }
}

// ---------------- K3: softmax over 192, in place ----------------
__global__ __launch_bounds__(256) void softmax_kernel()
{
    const int warp = threadIdx.x >> 5;
    const int lane = threadIdx.x & 31;
    const size_t row = (size_t)blockIdx.x * 8 + warp;
    float* p = g_e + row * LEN;

    float v[6];
    float m = -3.4e38f;
#pragma unroll
    for (int i = 0; i < 6; i++) { v[i] = p[lane + i * 32]; m = fmaxf(m, v[i]); }
#pragma unroll
    for (int s = 16; s > 0; s >>= 1) m = fmaxf(m, __shfl_xor_sync(0xffffffffu, m, s));
    float sum = 0.f;
#pragma unroll
    for (int i = 0; i < 6; i++) { v[i] = __expf(v[i] - m); sum += v[i]; }
#pragma unroll
    for (int s = 16; s > 0; s >>= 1) sum += __shfl_xor_sync(0xffffffffu, sum, s);
    const float inv = 1.f / sum;
#pragma unroll
    for (int i = 0; i < 6; i++) p[lane + i * 32] = v[i] * inv;
}

// ---------------- K4a: column apply -> writes col-part into d_out ----------------
// out[n,c,h,w] = sum_j attn_col[n,h,w,j] * v[n,c,j,w]      (block: (w, ctile, n))
__global__ __launch_bounds__(256) void colapply_kernel(float* __restrict__ out)
{
    __shared__ float Af[HH * 97];     // Af[h*97 + j]
    __shared__ float Vs[16][129];     // Vs[jj][cc]
    const int w  = blockIdx.x;
    const int c0 = blockIdx.y * 128;
    const int n  = blockIdx.z;
    const int tid = threadIdx.x;

    for (int e = tid; e < HH * HH; e += 256) {
        int h = e / HH, j = e % HH;
        Af[h * 97 + j] = g_e[((size_t)(n * HH + h) * WW + w) * LEN + WW + j];
    }

    const int tx = tid & 15;     // h-group (6)
    const int ty = tid >> 4;     // c-group (8)
    float acc[6][8];
#pragma unroll
    for (int i = 0; i < 6; i++)
#pragma unroll
        for (int k = 0; k < 8; k++) acc[i][k] = 0.f;

    for (int kb = 0; kb < HH; kb += 16) {
        __syncthreads();
#pragma unroll
        for (int t = 0; t < 8; t++) {
            int e = tid + t * 256;
            int jj = e >> 7, cc = e & 127;
            Vs[jj][cc] = g_v[((size_t)(n * CC + c0 + cc) * HH + kb + jj) * WW + w];
        }
        __syncthreads();
#pragma unroll
        for (int jj = 0; jj < 16; jj++) {
            int j = kb + jj;
            float a[6], b[8];
#pragma unroll
            for (int i = 0; i < 6; i++) a[i] = Af[(tx * 6 + i) * 97 + j];
#pragma unroll
            for (int k = 0; k < 8; k++) b[k] = Vs[jj][ty * 8 + k];
#pragma unroll
            for (int i = 0; i < 6; i++)
#pragma unroll
                for (int k = 0; k < 8; k++) acc[i][k] += a[i] * b[k];
        }
    }
#pragma unroll
    for (int i = 0; i < 6; i++)
#pragma unroll
        for (int k = 0; k < 8; k++)
            out[((size_t)(n * CC + c0 + ty * 8 + k) * HH + tx * 6 + i) * WW + w] = acc[i][k];
}

// ---------------- K4b: row apply + finalize ----------------
// out[n,c,h,w] = gamma * ( sum_v attn_row[n,h,w,v]*v[n,c,h,v] + out_colpart ) + x
__global__ __launch_bounds__(256) void rowapply_kernel(
    const float* __restrict__ x, const float* __restrict__ gamma, float* __restrict__ out)
{
    __shared__ float Af[WW * 97];     // Af[w*97 + v]
    __shared__ float Vs[16][129];     // Vs[vv][cc]
    const int h  = blockIdx.x;
    const int c0 = blockIdx.y * 128;
    const int n  = blockIdx.z;
    const int tid = threadIdx.x;

    for (int e = tid; e < WW * WW; e += 256) {
        int w_ = e / WW, v_ = e % WW;
        Af[w_ * 97 + v_] = g_e[((size_t)(n * HH + h) * WW + w_) * LEN + v_];
    }

    const int tx = tid & 15;    // w-group (6)
    const int ty = tid >> 4;    // c-group (8)
    float acc[6][8];
#pragma unroll
    for (int i = 0; i < 6; i++)
#pragma unroll
        for (int k = 0; k < 8; k++) acc[i][k] = 0.f;

    const float g = gamma[0];

    for (int kb = 0; kb < WW; kb += 16) {
        __syncthreads();
#pragma unroll
        for (int t = 0; t < 8; t++) {
            int e = tid + t * 256;
            int cc = e >> 4, vv = e & 15;
            Vs[vv][cc] = g_v[((size_t)(n * CC + c0 + cc) * HH + h) * WW + kb + vv];
        }
        __syncthreads();
#pragma unroll
        for (int vv = 0; vv < 16; vv++) {
            int v = kb + vv;
            float a[6], b[8];
#pragma unroll
            for (int i = 0; i < 6; i++) a[i] = Af[(tx * 6 + i) * 97 + v];
#pragma unroll
            for (int k = 0; k < 8; k++) b[k] = Vs[vv][ty * 8 + k];
#pragma unroll
            for (int i = 0; i < 6; i++)
#pragma unroll
                for (int k = 0; k < 8; k++) acc[i][k] += a[i] * b[k];
        }
    }
#pragma unroll
    for (int k = 0; k < 8; k++) {
#pragma unroll
        for (int i = 0; i < 6; i++) {
            size_t idx = ((size_t)(n * CC + c0 + ty * 8 + k) * HH + h) * WW + tx * 6 + i;
            out[idx] = g * (acc[i][k] + out[idx]) + x[idx];
        }
    }
}

// ---------------- launch ----------------
extern "C" void kernel_launch(void* const* d_in, const int* in_sizes, int n_in,
                              void* d_out, int out_size)
{
    const float* x     = (const float*)d_in[0];
    const float* wq    = (const float*)d_in[1];
    const float* bq    = (const float*)d_in[2];
    const float* wk    = (const float*)d_in[3];
    const float* bk    = (const float*)d_in[4];
    const float* wv    = (const float*)d_in[5];
    const float* bv    = (const float*)d_in[6];
    const float* gamma = (const float*)d_in[7];
    float* out = (float*)d_out;

    float* q; cudaGetSymbolAddress((void**)&q, g_q);
    float* k; cudaGetSymbolAddress((void**)&k, g_k);
    float* v; cudaGetSymbolAddress((void**)&v, g_v);

    // projections
    {
        dim3 gq(HW / 128, CQ / 64, NB);
        proj_kernel<<<gq, 256>>>(wq, bq, x, q, CQ);
        proj_kernel<<<gq, 256>>>(wk, bk, x, k, CQ);
        dim3 gv(HW / 128, CC / 64, NB);
        proj_kernel<<<gv, 256>>>(wv, bv, x, v, CC);
    }
    // energies
    erow_kernel<<<NB * HH, 256>>>();
    ecol_kernel<<<NB * WW, 256>>>();
    // softmax (73728 rows, 8 per block)
    softmax_kernel<<<(NB * HW) / 8, 256>>>();
    // column apply (writes every element of out)
    colapply_kernel<<<dim3(WW, CC / 128, NB), 256>>>(out);
    // row apply + gamma + residual (in-place finalize)
    rowapply_kernel<<<dim3(HH, CC / 128, NB), 256>>>(x, gamma, out);
}

// round 3
// speedup vs baseline: 2.0226x; 2.0226x over previous
#include <cuda_runtime.h>
#include <cstdint>

#define NB 8
#define CC 512
#define CQ 64
#define HH 96
#define WW 96
#define HW (HH*WW)          // 9216
#define LEN 192
#define NEGV -1e30f

// ---------------- scratch (device globals; no allocation allowed) ----------------
__device__ float g_q[(size_t)NB*CQ*HW];       //  18.9 MB
__device__ float g_k[(size_t)NB*CQ*HW];       //  18.9 MB
__device__ float g_v[(size_t)NB*CC*HW];       // 151 MB
__device__ float g_e[(size_t)NB*HW*LEN];      //  56.6 MB (energy -> attn in place)

// ---------------- tf32 mma helpers ----------------
__device__ __forceinline__ uint32_t cvt_tf32(float f) {
    uint32_t r;
    asm("cvt.rna.tf32.f32 %0, %1;" : "=r"(r) : "f"(f));
    return r;
}
__device__ __forceinline__ void mma_tf32(float (&d)[4], const uint32_t (&a)[4], const uint32_t (&b)[2]) {
    asm volatile(
        "mma.sync.aligned.m16n8k8.row.col.f32.tf32.tf32.f32 "
        "{%0,%1,%2,%3}, {%4,%5,%6,%7}, {%8,%9}, {%0,%1,%2,%3};\n"
        : "+f"(d[0]), "+f"(d[1]), "+f"(d[2]), "+f"(d[3])
        : "r"(a[0]), "r"(a[1]), "r"(a[2]), "r"(a[3]), "r"(b[0]), "r"(b[1]));
}
#define CP_ASYNC16(dst, src) asm volatile("cp.async.cg.shared.global [%0], [%1], 16;" :: "r"(dst), "l"(src))
#define CP_COMMIT            asm volatile("cp.async.commit_group;")
#define CP_WAIT0             asm volatile("cp.async.wait_group 0;")

// ---------------- K1: projection GEMM on tensor cores (tf32) ----------------
// out[n][o][p] = sum_c Wt[o][c] * x[n][c][p] + bias[o]
// BM=64, BN=128, BK=32, 256 threads (8 warps: 2 M x 4 N), warp tile 32x32.
// Double-buffered cp.async; XOR-swizzled smem (conflict-free fragment loads).
__global__ __launch_bounds__(256) void proj_mma(
    const float* __restrict__ Wt, const float* __restrict__ bias,
    const float* __restrict__ x, float* __restrict__ out, int O)
{
    __shared__ float As[2][64 * 32];     //  8 KB/stage: As[m][k], k-chunks XOR (m&7)<<2
    __shared__ float Bs[2][32 * 128];    // 16 KB/stage: Bs[k][n], n-chunks XOR (k&3)<<3

    const int n  = blockIdx.z;
    const int m0 = blockIdx.y * 64;
    const int p0 = blockIdx.x * 128;
    const float* B = x + (size_t)n * CC * HW;
    float* Cp      = out + (size_t)n * O * HW;

    const int tid  = threadIdx.x;
    const int warp = tid >> 5, lane = tid & 31;
    const int wm = warp >> 2, wn = warp & 3;
    const int lr = lane >> 2, lc = lane & 3;

    const uint32_t aBase = (uint32_t)__cvta_generic_to_shared(&As[0][0]);
    const uint32_t bBase = (uint32_t)__cvta_generic_to_shared(&Bs[0][0]);

    float acc[2][4][4] = {};

    auto issue = [&](int kt) {
        const int buf = kt & 1;
        const uint32_t ab = aBase + buf * 64 * 32 * 4;
        const uint32_t bb = bBase + buf * 32 * 128 * 4;
        const int k0 = kt * 32;
        // A: 64 rows x 8 chunks(16B) = 512 chunks, 2 per thread
#pragma unroll
        for (int i = 0; i < 2; i++) {
            int e = tid + i * 256;
            int m = e >> 3, kc = e & 7;
            const float* src = Wt + (size_t)(m0 + m) * CC + k0 + kc * 4;
            uint32_t dst = ab + (uint32_t)(m * 32 + ((kc * 4) ^ ((m & 7) << 2))) * 4;
            CP_ASYNC16(dst, src);
        }
        // B: 32 rows x 32 chunks = 1024 chunks, 4 per thread
#pragma unroll
        for (int i = 0; i < 4; i++) {
            int e = tid + i * 256;
            int k = e >> 5, c = e & 31;
            const float* src = B + (size_t)(k0 + k) * HW + p0 + c * 4;
            uint32_t dst = bb + (uint32_t)(k * 128 + ((c * 4) ^ ((k & 3) << 3))) * 4;
            CP_ASYNC16(dst, src);
        }
        CP_COMMIT;
    };

    issue(0);
    for (int kt = 0; kt < 16; kt++) {
        CP_WAIT0;
        __syncthreads();
        if (kt + 1 < 16) issue(kt + 1);

        const int buf = kt & 1;
        const float* Ab = &As[buf][0];
        const float* Bb = &Bs[buf][0];
#pragma unroll
        for (int ks = 0; ks < 4; ks++) {
            const int kk = ks * 8;
            uint32_t afr[2][4], bfr[4][2];
#pragma unroll
            for (int t = 0; t < 2; t++) {
                int m  = wm * 32 + t * 16 + lr;
                int sw = (m & 7) << 2;          // (m+8)&7 == m&7, consistent for a1/a3
                int kb = kk + lc;
                afr[t][0] = cvt_tf32(Ab[m * 32       + (kb ^ sw)]);
                afr[t][1] = cvt_tf32(Ab[(m + 8) * 32 + (kb ^ sw)]);
                afr[t][2] = cvt_tf32(Ab[m * 32       + ((kb + 4) ^ sw)]);
                afr[t][3] = cvt_tf32(Ab[(m + 8) * 32 + ((kb + 4) ^ sw)]);
            }
#pragma unroll
            for (int nt = 0; nt < 4; nt++) {
                int nn  = wn * 32 + nt * 8 + lr;
                int col = nn ^ (lc << 3);
                bfr[nt][0] = cvt_tf32(Bb[(kk + lc) * 128     + col]);
                bfr[nt][1] = cvt_tf32(Bb[(kk + lc + 4) * 128 + col]);
            }
#pragma unroll
            for (int t = 0; t < 2; t++)
#pragma unroll
                for (int nt = 0; nt < 4; nt++)
                    mma_tf32(acc[t][nt], afr[t], bfr[nt]);
        }
        __syncthreads();
    }

    // epilogue: bias + float2 stores
#pragma unroll
    for (int t = 0; t < 2; t++) {
        int r0 = m0 + wm * 32 + t * 16 + lr;
        float bv0 = bias[r0], bv1 = bias[r0 + 8];
#pragma unroll
        for (int nt = 0; nt < 4; nt++) {
            int col = p0 + wn * 32 + nt * 8 + lc * 2;
            float2 v0 = make_float2(acc[t][nt][0] + bv0, acc[t][nt][1] + bv0);
            float2 v1 = make_float2(acc[t][nt][2] + bv1, acc[t][nt][3] + bv1);
            *(float2*)&Cp[(size_t)r0 * HW + col]       = v0;
            *(float2*)&Cp[(size_t)(r0 + 8) * HW + col] = v1;
        }
    }
}

// ---------------- K2a: row energies ----------------
__global__ __launch_bounds__(256) void erow_kernel()
{
    __shared__ float Qs[CQ * WW];
    __shared__ float Ks[CQ * WW];
    const int n = blockIdx.x / HH;
    const int h = blockIdx.x % HH;
    const int tid = threadIdx.x;

    const float* qb = g_q + (size_t)n * CQ * HW + (size_t)h * WW;
    const float* kb = g_k + (size_t)n * CQ * HW + (size_t)h * WW;
    for (int e = tid; e < CQ * WW; e += 256) {
        int c = e / WW, w = e % WW;
        Qs[e] = qb[(size_t)c * HW + w];
        Ks[e] = kb[(size_t)c * HW + w];
    }
    __syncthreads();

    const int tw = tid >> 4;
    const int tv = tid & 15;
    float acc[6][6];
#pragma unroll
    for (int i = 0; i < 6; i++)
#pragma unroll
        for (int j = 0; j < 6; j++) acc[i][j] = 0.f;

    for (int c = 0; c < CQ; c++) {
        float a[6], b[6];
#pragma unroll
        for (int i = 0; i < 6; i++) a[i] = Qs[c * WW + tw * 6 + i];
#pragma unroll
        for (int j = 0; j < 6; j++) b[j] = Ks[c * WW + tv * 6 + j];
#pragma unroll
        for (int i = 0; i < 6; i++)
#pragma unroll
            for (int j = 0; j < 6; j++) acc[i][j] += a[i] * b[j];
    }
    float* ep = g_e + ((size_t)(n * HH + h) * WW) * LEN;
#pragma unroll
    for (int i = 0; i < 6; i++)
#pragma unroll
        for (int j = 0; j < 6; j++)
            ep[(size_t)(tw * 6 + i) * LEN + tv * 6 + j] = acc[i][j];
}

// ---------------- K2b: column energies ----------------
__global__ __launch_bounds__(256) void ecol_kernel()
{
    __shared__ float Qs[CQ * HH];
    __shared__ float Ks[CQ * HH];
    const int n = blockIdx.x / WW;
    const int w = blockIdx.x % WW;
    const int tid = threadIdx.x;

    for (int e = tid; e < CQ * HH; e += 256) {
        int c = e / HH, h = e % HH;
        size_t gi = ((size_t)(n * CQ + c) * HH + h) * WW + w;
        Qs[e] = g_q[gi];
        Ks[e] = g_k[gi];
    }
    __syncthreads();

    const int th = tid >> 4;
    const int tj = tid & 15;
    float acc[6][6];
#pragma unroll
    for (int i = 0; i < 6; i++)
#pragma unroll
        for (int j = 0; j < 6; j++) acc[i][j] = 0.f;

    for (int c = 0; c < CQ; c++) {
        float a[6], b[6];
#pragma unroll
        for (int i = 0; i < 6; i++) a[i] = Qs[c * HH + th * 6 + i];
#pragma unroll
        for (int j = 0; j < 6; j++) b[j] = Ks[c * HH + tj * 6 + j];
#pragma unroll
        for (int i = 0; i < 6; i++)
#pragma unroll
            for (int j = 0; j < 6; j++) acc[i][j] += a[i] * b[j];
    }
#pragma unroll
    for (int i = 0; i < 6; i++) {
        int h = th * 6 + i;
        float* ep = g_e + ((size_t)(n * HH + h) * WW + w) * LEN + WW;
#pragma unroll
        for (int j = 0; j < 6; j++) {
            int jc = tj * 6 + j;
            ep[jc] = (jc == h) ? NEGV : acc[i][j];
        }
    }
}

// ---------------- K3: softmax over 192, in place ----------------
__global__ __launch_bounds__(256) void softmax_kernel()
{
    const int warp = threadIdx.x >> 5;
    const int lane = threadIdx.x & 31;
    const size_t row = (size_t)blockIdx.x * 8 + warp;
    float* p = g_e + row * LEN;

    float v[6];
    float m = -3.4e38f;
#pragma unroll
    for (int i = 0; i < 6; i++) { v[i] = p[lane + i * 32]; m = fmaxf(m, v[i]); }
#pragma unroll
    for (int s = 16; s > 0; s >>= 1) m = fmaxf(m, __shfl_xor_sync(0xffffffffu, m, s));
    float sum = 0.f;
#pragma unroll
    for (int i = 0; i < 6; i++) { v[i] = __expf(v[i] - m); sum += v[i]; }
#pragma unroll
    for (int s = 16; s > 0; s >>= 1) sum += __shfl_xor_sync(0xffffffffu, sum, s);
    const float inv = 1.f / sum;
#pragma unroll
    for (int i = 0; i < 6; i++) p[lane + i * 32] = v[i] * inv;
}

// ---------------- K4a: column apply -> writes col-part into d_out ----------------
__global__ __launch_bounds__(256) void colapply_kernel(float* __restrict__ out)
{
    __shared__ float Af[HH * 97];
    __shared__ float Vs[16][129];
    const int w  = blockIdx.x;
    const int c0 = blockIdx.y * 128;
    const int n  = blockIdx.z;
    const int tid = threadIdx.x;

    for (int e = tid; e < HH * HH; e += 256) {
        int h = e / HH, j = e % HH;
        Af[h * 97 + j] = g_e[((size_t)(n * HH + h) * WW + w) * LEN + WW + j];
    }

    const int tx = tid & 15;
    const int ty = tid >> 4;
    float acc[6][8];
#pragma unroll
    for (int i = 0; i < 6; i++)
#pragma unroll
        for (int k = 0; k < 8; k++) acc[i][k] = 0.f;

    for (int kb = 0; kb < HH; kb += 16) {
        __syncthreads();
#pragma unroll
        for (int t = 0; t < 8; t++) {
            int e = tid + t * 256;
            int jj = e >> 7, cc = e & 127;
            Vs[jj][cc] = g_v[((size_t)(n * CC + c0 + cc) * HH + kb + jj) * WW + w];
        }
        __syncthreads();
#pragma unroll
        for (int jj = 0; jj < 16; jj++) {
            int j = kb + jj;
            float a[6], b[8];
#pragma unroll
            for (int i = 0; i < 6; i++) a[i] = Af[(tx * 6 + i) * 97 + j];
#pragma unroll
            for (int k = 0; k < 8; k++) b[k] = Vs[jj][ty * 8 + k];
#pragma unroll
            for (int i = 0; i < 6; i++)
#pragma unroll
                for (int k = 0; k < 8; k++) acc[i][k] += a[i] * b[k];
        }
    }
#pragma unroll
    for (int i = 0; i < 6; i++)
#pragma unroll
        for (int k = 0; k < 8; k++)
            out[((size_t)(n * CC + c0 + ty * 8 + k) * HH + tx * 6 + i) * WW + w] = acc[i][k];
}

// ---------------- K4b: row apply + finalize ----------------
__global__ __launch_bounds__(256) void rowapply_kernel(
    const float* __restrict__ x, const float* __restrict__ gamma, float* __restrict__ out)
{
    __shared__ float Af[WW * 97];
    __shared__ float Vs[16][129];
    const int h  = blockIdx.x;
    const int c0 = blockIdx.y * 128;
    const int n  = blockIdx.z;
    const int tid = threadIdx.x;

    for (int e = tid; e < WW * WW; e += 256) {
        int w_ = e / WW, v_ = e % WW;
        Af[w_ * 97 + v_] = g_e[((size_t)(n * HH + h) * WW + w_) * LEN + v_];
    }

    const int tx = tid & 15;
    const int ty = tid >> 4;
    float acc[6][8];
#pragma unroll
    for (int i = 0; i < 6; i++)
#pragma unroll
        for (int k = 0; k < 8; k++) acc[i][k] = 0.f;

    const float g = gamma[0];

    for (int kb = 0; kb < WW; kb += 16) {
        __syncthreads();
#pragma unroll
        for (int t = 0; t < 8; t++) {
            int e = tid + t * 256;
            int cc = e >> 4, vv = e & 15;
            Vs[vv][cc] = g_v[((size_t)(n * CC + c0 + cc) * HH + h) * WW + kb + vv];
        }
        __syncthreads();
#pragma unroll
        for (int vv = 0; vv < 16; vv++) {
            int v = kb + vv;
            float a[6], b[8];
#pragma unroll
            for (int i = 0; i < 6; i++) a[i] = Af[(tx * 6 + i) * 97 + v];
#pragma unroll
            for (int k = 0; k < 8; k++) b[k] = Vs[vv][ty * 8 + k];
#pragma unroll
            for (int i = 0; i < 6; i++)
#pragma unroll
                for (int k = 0; k < 8; k++) acc[i][k] += a[i] * b[k];
        }
    }
#pragma unroll
    for (int k = 0; k < 8; k++) {
#pragma unroll
        for (int i = 0; i < 6; i++) {
            size_t idx = ((size_t)(n * CC + c0 + ty * 8 + k) * HH + h) * WW + tx * 6 + i;
            out[idx] = g * (acc[i][k] + out[idx]) + x[idx];
        }
    }
}

// ---------------- launch ----------------
extern "C" void kernel_launch(void* const* d_in, const int* in_sizes, int n_in,
                              void* d_out, int out_size)
{
    const float* x     = (const float*)d_in[0];
    const float* wq    = (const float*)d_in[1];
    const float* bq    = (const float*)d_in[2];
    const float* wk    = (const float*)d_in[3];
    const float* bk    = (const float*)d_in[4];
    const float* wv    = (const float*)d_in[5];
    const float* bv    = (const float*)d_in[6];
    const float* gamma = (const float*)d_in[7];
    float* out = (float*)d_out;

    float* q; cudaGetSymbolAddress((void**)&q, g_q);
    float* k; cudaGetSymbolAddress((void**)&k, g_k);
    float* v; cudaGetSymbolAddress((void**)&v, g_v);

    // projections on tensor cores (tf32)
    {
        dim3 gq(HW / 128, CQ / 64, NB);
        proj_mma<<<gq, 256>>>(wq, bq, x, q, CQ);
        proj_mma<<<gq, 256>>>(wk, bk, x, k, CQ);
        dim3 gv(HW / 128, CC / 64, NB);
        proj_mma<<<gv, 256>>>(wv, bv, x, v, CC);
    }
    // energies
    erow_kernel<<<NB * HH, 256>>>();
    ecol_kernel<<<NB * WW, 256>>>();
    // softmax (73728 rows, 8 per block)
    softmax_kernel<<<(NB * HW) / 8, 256>>>();
    // column apply (writes every element of out)
    colapply_kernel<<<dim3(WW, CC / 128, NB), 256>>>(out);
    // row apply + gamma + residual (in-place finalize)
    rowapply_kernel<<<dim3(HH, CC / 128, NB), 256>>>(x, gamma, out);
}